// round 12
// baseline (speedup 1.0000x reference)
#include <cuda_runtime.h>
#include <cuda_fp16.h>

#define NN 10000
#define TT 2
#define CC 64
#define HH 4
#define CO 64
#define HC 256
#define EE 160000
#define MROWS (TT*NN)

// scratch (static device allocations; no cudaMalloc allowed)
__device__ __half g_xlh[MROWS * HC];   // x_l in fp16 (gathered tensor)
__device__ float  g_xr[MROWS * HC];
__device__ __half g_mhah[MROWS * HC];  // x_mha in fp16
__device__ int    g_deg[NN];           // zero-initialized; k_scan re-zeroes after use
__device__ int    g_rowptr[NN + 1];
__device__ int    g_cursor[NN];
__device__ int    g_srcs[EE];

// 4 edges per thread via int4
__global__ void k_hist(const int* __restrict__ ei) {
    int i = blockIdx.x * blockDim.x + threadIdx.x;
    if (i < EE / 4) {
        int4 d4 = ((const int4*)(ei + EE))[i];
        atomicAdd(&g_deg[d4.x], 1);
        atomicAdd(&g_deg[d4.y], 1);
        atomicAdd(&g_deg[d4.z], 1);
        atomicAdd(&g_deg[d4.w], 1);
    }
}

__global__ void __launch_bounds__(1024) k_scan() {
    __shared__ int sc[1024];
    int tid = threadIdx.x;
    const int CH = (NN + 1023) / 1024;  // 10
    int base = tid * CH;
    int local = 0;
    for (int j = 0; j < CH; j++) {
        int idx = base + j;
        if (idx < NN) local += g_deg[idx];
    }
    sc[tid] = local;
    __syncthreads();
    for (int off = 1; off < 1024; off <<= 1) {
        int v = (tid >= off) ? sc[tid - off] : 0;
        __syncthreads();
        sc[tid] += v;
        __syncthreads();
    }
    int run = sc[tid] - local;  // exclusive prefix
    for (int j = 0; j < CH; j++) {
        int idx = base + j;
        if (idx < NN) {
            int d = g_deg[idx];
            g_rowptr[idx] = run;
            g_cursor[idx] = run;
            run += d;
            g_deg[idx] = 0;   // reset for next invocation (replay-deterministic)
        }
    }
    if (tid == 1023) g_rowptr[NN] = sc[1023];
}

__global__ void k_scatter(const int* __restrict__ ei) {
    int i = blockIdx.x * blockDim.x + threadIdx.x;
    if (i < EE / 4) {
        int4 s4 = ((const int4*)ei)[i];
        int4 d4 = ((const int4*)(ei + EE))[i];
        g_srcs[atomicAdd(&g_cursor[d4.x], 1)] = s4.x;
        g_srcs[atomicAdd(&g_cursor[d4.y], 1)] = s4.y;
        g_srcs[atomicAdd(&g_cursor[d4.z], 1)] = s4.z;
        g_srcs[atomicAdd(&g_cursor[d4.w], 1)] = s4.w;
    }
}

// ================= Tensor-core dual GEMM =================
#define XS_STRIDE 72
#define GEMM_SMEM ((128 * XS_STRIDE + 512 * XS_STRIDE) * 2)

__device__ __forceinline__ unsigned ldsm(const __half* p) {
    return *(const unsigned*)p;
}

__device__ __forceinline__ void mma16816(float* d, const unsigned* a,
                                         unsigned b0, unsigned b1) {
    asm volatile(
        "mma.sync.aligned.m16n8k16.row.col.f32.f16.f16.f32 "
        "{%0,%1,%2,%3}, {%4,%5,%6,%7}, {%8,%9}, {%0,%1,%2,%3};\n"
        : "+f"(d[0]), "+f"(d[1]), "+f"(d[2]), "+f"(d[3])
        : "r"(a[0]), "r"(a[1]), "r"(a[2]), "r"(a[3]), "r"(b0), "r"(b1));
}

__global__ void __launch_bounds__(256) k_gemm(
    const float* __restrict__ x,
    const float* __restrict__ Wl, const float* __restrict__ bl,
    const float* __restrict__ Wr, const float* __restrict__ br)
{
    extern __shared__ __half smem[];
    __half* xs = smem;                       // [128][72]
    __half* Wt = smem + 128 * XS_STRIDE;     // [512][72]

    int tid = threadIdx.x;
    int row0 = blockIdx.x * 128;

#pragma unroll
    for (int it = 0; it < 32; it++) {
        int flat = it * 256 + tid;
        int r = flat >> 6, c = flat & 63;
        int grow = row0 + r;
        float v = (grow < MROWS) ? x[grow * CC + c] : 0.f;
        xs[r * XS_STRIDE + c] = __float2half(v);
    }
#pragma unroll
    for (int it = 0; it < 128; it++) {
        int flat = it * 256 + tid;
        int k = flat >> 9, n = flat & 511;
        float v = (n < HC) ? Wl[k * HC + n] : Wr[k * HC + (n - HC)];
        Wt[n * XS_STRIDE + k] = __float2half(v);
    }
    __syncthreads();

    int lane = tid & 31;
    int wid = tid >> 5;
    int g = lane >> 2;
    int q = lane & 3;
    int wm = wid * 16;

    unsigned Areg[4][4];
#pragma unroll
    for (int ks = 0; ks < 4; ks++) {
        int kb = ks * 16 + q * 2;
        Areg[ks][0] = ldsm(&xs[(wm + g) * XS_STRIDE + kb]);
        Areg[ks][1] = ldsm(&xs[(wm + g + 8) * XS_STRIDE + kb]);
        Areg[ks][2] = ldsm(&xs[(wm + g) * XS_STRIDE + kb + 8]);
        Areg[ks][3] = ldsm(&xs[(wm + g + 8) * XS_STRIDE + kb + 8]);
    }

    int row_lo = row0 + wm + g;
    int row_hi = row_lo + 8;

#pragma unroll 1
    for (int chunk = 0; chunk < 8; chunk++) {
        float d[8][4];
#pragma unroll
        for (int nt = 0; nt < 8; nt++)
#pragma unroll
            for (int e = 0; e < 4; e++) d[nt][e] = 0.f;

#pragma unroll
        for (int ks = 0; ks < 4; ks++) {
            int kb = ks * 16 + q * 2;
#pragma unroll
            for (int nt = 0; nt < 8; nt++) {
                int n = chunk * 64 + nt * 8 + g;
                unsigned b0 = ldsm(&Wt[n * XS_STRIDE + kb]);
                unsigned b1 = ldsm(&Wt[n * XS_STRIDE + kb + 8]);
                mma16816(d[nt], Areg[ks], b0, b1);
            }
        }

#pragma unroll
        for (int nt = 0; nt < 8; nt++) {
            int colg = chunk * 64 + nt * 8 + q * 2;
            if (colg < HC) {
                float b0v = bl[colg], b1v = bl[colg + 1];
                if (row_lo < MROWS) {
                    __half2 h = __floats2half2_rn(d[nt][0] + b0v, d[nt][1] + b1v);
                    *(__half2*)&g_xlh[row_lo * HC + colg] = h;
                }
                if (row_hi < MROWS) {
                    __half2 h = __floats2half2_rn(d[nt][2] + b0v, d[nt][3] + b1v);
                    *(__half2*)&g_xlh[row_hi * HC + colg] = h;
                }
            } else {
                int c = colg - HC;
                float b0v = br[c], b1v = br[c + 1];
                if (row_lo < MROWS) {
                    float2 f = make_float2(d[nt][0] + b0v, d[nt][1] + b1v);
                    *(float2*)&g_xr[row_lo * HC + c] = f;
                }
                if (row_hi < MROWS) {
                    float2 f = make_float2(d[nt][2] + b0v, d[nt][3] + b1v);
                    *(float2*)&g_xr[row_hi * HC + c] = f;
                }
            }
        }
    }
}

// GAT aggregation: one WARP per node n, BOTH time-slices in one pass.
// Lane L owns head (L>>3), dims [(L&7)*8, +8).
// Per edge: 2 independent 16B gathers (t0 row, t1 row at +TOFF), shared index.
__device__ __forceinline__ int get_src(int k, int s0, int s1, int base) {
    if (k < 32) return __shfl_sync(0xffffffffu, s0, k);
    if (k < 64) return __shfl_sync(0xffffffffu, s1, k - 32);
    return g_srcs[base + k];
}

__device__ __forceinline__ void h2f8(uint4 u, float4& a0, float4& a1) {
    float2 f0 = __half22float2(*(__half2*)&u.x);
    float2 f1 = __half22float2(*(__half2*)&u.y);
    float2 f2 = __half22float2(*(__half2*)&u.z);
    float2 f3 = __half22float2(*(__half2*)&u.w);
    a0 = make_float4(f0.x, f0.y, f1.x, f1.y);
    a1 = make_float4(f2.x, f2.y, f3.x, f3.y);
}

#define TOFF (NN * (HC / 8))

__global__ void __launch_bounds__(256) k_agg(
    const float* __restrict__ att,
    const float* __restrict__ bias)
{
    int n = blockIdx.x * 8 + (threadIdx.x >> 5);   // node id
    if (n >= NN) return;
    int lane = threadIdx.x & 31;
    int f4 = lane * 2;

    // x_r rows for both t
    const float4* xrA = (const float4*)&g_xr[n * HC];          // t=0
    const float4* xrB = (const float4*)&g_xr[(NN + n) * HC];   // t=1
    float4 xa0 = xrA[f4], xa1 = xrA[f4 + 1];
    float4 xb0 = xrB[f4], xb1 = xrB[f4 + 1];
    float4 at0 = ((const float4*)att)[f4];
    float4 at1 = ((const float4*)att)[f4 + 1];

    int base = g_rowptr[n];
    int deg = g_rowptr[n + 1] - base;

    int s0 = (lane < deg) ? g_srcs[base + lane] : 0;
    int s1 = (32 + lane < deg) ? g_srcs[base + 32 + lane] : 0;

    float denA = 0.f, denB = 0.f;
    float4 aA0 = make_float4(0.f, 0.f, 0.f, 0.f);
    float4 aA1 = make_float4(0.f, 0.f, 0.f, 0.f);
    float4 aB0 = make_float4(0.f, 0.f, 0.f, 0.f);
    float4 aB1 = make_float4(0.f, 0.f, 0.f, 0.f);
    const uint4* xlh4 = (const uint4*)g_xlh;

    // 3-deep pipeline, 2 loads per slot (t0, t1)
    uint4 Pa0, Pb0, Pa1, Pb1, Pa2, Pb2;
    if (deg > 0) {
        int idx = get_src(0, s0, s1, base) * (HC / 8) + lane;
        Pa0 = xlh4[idx]; Pb0 = xlh4[idx + TOFF];
    }
    if (deg > 1) {
        int idx = get_src(1, s0, s1, base) * (HC / 8) + lane;
        Pa1 = xlh4[idx]; Pb1 = xlh4[idx + TOFF];
    }
    if (deg > 2) {
        int idx = get_src(2, s0, s1, base) * (HC / 8) + lane;
        Pa2 = xlh4[idx]; Pb2 = xlh4[idx + TOFF];
    }

#define AGG_T(u, XR0, XR1, DEN, ACC0, ACC1)                                  \
    {                                                                        \
        float4 a0, a1;                                                       \
        h2f8(u, a0, a1);                                                     \
        float v, p;                                                          \
        v = a0.x + XR0.x; v = fmaxf(v, 0.2f * v); p = v * at0.x;             \
        v = a0.y + XR0.y; v = fmaxf(v, 0.2f * v); p = fmaf(v, at0.y, p);     \
        v = a0.z + XR0.z; v = fmaxf(v, 0.2f * v); p = fmaf(v, at0.z, p);     \
        v = a0.w + XR0.w; v = fmaxf(v, 0.2f * v); p = fmaf(v, at0.w, p);     \
        v = a1.x + XR1.x; v = fmaxf(v, 0.2f * v); p = fmaf(v, at1.x, p);     \
        v = a1.y + XR1.y; v = fmaxf(v, 0.2f * v); p = fmaf(v, at1.y, p);     \
        v = a1.z + XR1.z; v = fmaxf(v, 0.2f * v); p = fmaf(v, at1.z, p);     \
        v = a1.w + XR1.w; v = fmaxf(v, 0.2f * v); p = fmaf(v, at1.w, p);     \
        p += __shfl_xor_sync(0xffffffffu, p, 1);                             \
        p += __shfl_xor_sync(0xffffffffu, p, 2);                             \
        p += __shfl_xor_sync(0xffffffffu, p, 4);                             \
        float e = __expf(p);                                                 \
        DEN += e;                                                            \
        ACC0.x = fmaf(e, a0.x, ACC0.x);                                      \
        ACC0.y = fmaf(e, a0.y, ACC0.y);                                      \
        ACC0.z = fmaf(e, a0.z, ACC0.z);                                      \
        ACC0.w = fmaf(e, a0.w, ACC0.w);                                      \
        ACC1.x = fmaf(e, a1.x, ACC1.x);                                      \
        ACC1.y = fmaf(e, a1.y, ACC1.y);                                      \
        ACC1.z = fmaf(e, a1.z, ACC1.z);                                      \
        ACC1.w = fmaf(e, a1.w, ACC1.w);                                      \
    }

#define AGG_STEP(RA, RB)                                                     \
    {                                                                        \
        uint4 ua = RA, ub = RB;                                              \
        if (k + 3 < deg) {                                                   \
            int idx = get_src(k + 3, s0, s1, base) * (HC / 8) + lane;        \
            RA = xlh4[idx]; RB = xlh4[idx + TOFF];                           \
        }                                                                    \
        AGG_T(ua, xa0, xa1, denA, aA0, aA1);                                 \
        AGG_T(ub, xb0, xb1, denB, aB0, aB1);                                 \
        k++;                                                                 \
    }

    int k = 0;
    while (k < deg) {
        AGG_STEP(Pa0, Pb0);
        if (k >= deg) break;
        AGG_STEP(Pa1, Pb1);
        if (k >= deg) break;
        AGG_STEP(Pa2, Pb2);
    }
#undef AGG_STEP
#undef AGG_T

    float invA = (deg > 0) ? 1.0f / denA : 0.f;
    float invB = (deg > 0) ? 1.0f / denB : 0.f;
    const float4* b4 = (const float4*)bias;
    float4 bb0 = b4[f4], bb1 = b4[f4 + 1];

    {
        __half2 h0 = __floats2half2_rn(fmaxf(fmaf(aA0.x, invA, bb0.x), 0.f),
                                       fmaxf(fmaf(aA0.y, invA, bb0.y), 0.f));
        __half2 h1 = __floats2half2_rn(fmaxf(fmaf(aA0.z, invA, bb0.z), 0.f),
                                       fmaxf(fmaf(aA0.w, invA, bb0.w), 0.f));
        __half2 h2 = __floats2half2_rn(fmaxf(fmaf(aA1.x, invA, bb1.x), 0.f),
                                       fmaxf(fmaf(aA1.y, invA, bb1.y), 0.f));
        __half2 h3 = __floats2half2_rn(fmaxf(fmaf(aA1.z, invA, bb1.z), 0.f),
                                       fmaxf(fmaf(aA1.w, invA, bb1.w), 0.f));
        uint4 pk;
        pk.x = *(unsigned*)&h0; pk.y = *(unsigned*)&h1;
        pk.z = *(unsigned*)&h2; pk.w = *(unsigned*)&h3;
        ((uint4*)g_mhah)[n * (HC / 8) + lane] = pk;
    }
    {
        __half2 h0 = __floats2half2_rn(fmaxf(fmaf(aB0.x, invB, bb0.x), 0.f),
                                       fmaxf(fmaf(aB0.y, invB, bb0.y), 0.f));
        __half2 h1 = __floats2half2_rn(fmaxf(fmaf(aB0.z, invB, bb0.z), 0.f),
                                       fmaxf(fmaf(aB0.w, invB, bb0.w), 0.f));
        __half2 h2 = __floats2half2_rn(fmaxf(fmaf(aB1.x, invB, bb1.x), 0.f),
                                       fmaxf(fmaf(aB1.y, invB, bb1.y), 0.f));
        __half2 h3 = __floats2half2_rn(fmaxf(fmaf(aB1.z, invB, bb1.z), 0.f),
                                       fmaxf(fmaf(aB1.w, invB, bb1.w), 0.f));
        uint4 pk;
        pk.x = *(unsigned*)&h0; pk.y = *(unsigned*)&h1;
        pk.z = *(unsigned*)&h2; pk.w = *(unsigned*)&h3;
        ((uint4*)g_mhah)[(NN + n) * (HC / 8) + lane] = pk;
    }
}

// ============ Tensor-core projection + residual + LayerNorm + relu ============
#define PJ_STRIDE 264
#define PROJ_SMEM ((64 * PJ_STRIDE + 64 * PJ_STRIDE) * 2)

__global__ void __launch_bounds__(256) k_proj(
    const float* __restrict__ x,
    const float* __restrict__ Wp, const float* __restrict__ bp,
    const float* __restrict__ gam, const float* __restrict__ bet,
    float* __restrict__ out)
{
    extern __shared__ __half psm[];
    __half* xs = psm;                      // [64][264]
    __half* Wt = psm + 64 * PJ_STRIDE;     // [64 n][264 k]
    float* ys = (float*)psm;               // [64][68], aliases xs after MMA

    int tid = threadIdx.x;
    int row0 = blockIdx.x * 64;

    const uint4* src = (const uint4*)g_mhah;
#pragma unroll
    for (int it = 0; it < 8; it++) {
        int flat = it * 256 + tid;
        int r = flat >> 5, u = flat & 31;
        int grow = row0 + r;
        uint4 v = make_uint4(0u, 0u, 0u, 0u);
        if (grow < MROWS) v = src[grow * (HC / 8) + u];
        *(uint4*)&xs[r * PJ_STRIDE + u * 8] = v;
    }
#pragma unroll
    for (int it = 0; it < 64; it++) {
        int flat = it * 256 + tid;
        int k = flat >> 6, n = flat & 63;
        Wt[n * PJ_STRIDE + k] = __float2half(Wp[k * CO + n]);
    }
    __syncthreads();

    int lane = tid & 31, wid = tid >> 5;
    int g = lane >> 2, q = lane & 3;
    int wm = (wid & 3) * 16;
    int nh = (wid >> 2) * 32;

    float d[4][4];
#pragma unroll
    for (int nt = 0; nt < 4; nt++)
#pragma unroll
        for (int e = 0; e < 4; e++) d[nt][e] = 0.f;

#pragma unroll 4
    for (int ks = 0; ks < 16; ks++) {
        int kb = ks * 16 + q * 2;
        unsigned a[4];
        a[0] = ldsm(&xs[(wm + g) * PJ_STRIDE + kb]);
        a[1] = ldsm(&xs[(wm + g + 8) * PJ_STRIDE + kb]);
        a[2] = ldsm(&xs[(wm + g) * PJ_STRIDE + kb + 8]);
        a[3] = ldsm(&xs[(wm + g + 8) * PJ_STRIDE + kb + 8]);
#pragma unroll
        for (int nt = 0; nt < 4; nt++) {
            int n = nh + nt * 8 + g;
            unsigned b0 = ldsm(&Wt[n * PJ_STRIDE + kb]);
            unsigned b1 = ldsm(&Wt[n * PJ_STRIDE + kb + 8]);
            mma16816(d[nt], a, b0, b1);
        }
    }
    __syncthreads();

#pragma unroll
    for (int nt = 0; nt < 4; nt++) {
        int c = nh + nt * 8 + q * 2;
        float b0v = bp[c], b1v = bp[c + 1];
        int rl = wm + g, rh = wm + g + 8;
        int gl = row0 + rl, gh = row0 + rh;
        if (gl < MROWS) {
            ys[rl * 68 + c]     = d[nt][0] + b0v + x[gl * CC + c];
            ys[rl * 68 + c + 1] = d[nt][1] + b1v + x[gl * CC + c + 1];
        }
        if (gh < MROWS) {
            ys[rh * 68 + c]     = d[nt][2] + b0v + x[gh * CC + c];
            ys[rh * 68 + c + 1] = d[nt][3] + b1v + x[gh * CC + c + 1];
        }
    }
    __syncthreads();

    float g0 = gam[lane], g1 = gam[lane + 32];
    float b0 = bet[lane], b1 = bet[lane + 32];
#pragma unroll
    for (int r = 0; r < 8; r++) {
        int row = wid * 8 + r;
        int grow = row0 + row;
        if (grow >= MROWS) break;
        float v0 = ys[row * 68 + lane];
        float v1 = ys[row * 68 + lane + 32];
        float sv = v0 + v1;
        float sq = v0 * v0 + v1 * v1;
#pragma unroll
        for (int off = 16; off; off >>= 1) {
            sv += __shfl_xor_sync(0xffffffffu, sv, off);
            sq += __shfl_xor_sync(0xffffffffu, sq, off);
        }
        float mu = sv * (1.f / 64.f);
        float var = sq * (1.f / 64.f) - mu * mu;
        float rstd = rsqrtf(var + 1e-5f);
        float y0 = (v0 - mu) * rstd * g0 + b0;
        float y1 = (v1 - mu) * rstd * g1 + b1;
        out[grow * CC + lane]      = fmaxf(y0, 0.f);
        out[grow * CC + lane + 32] = fmaxf(y1, 0.f);
    }
}

extern "C" void kernel_launch(void* const* d_in, const int* in_sizes, int n_in,
                              void* d_out, int out_size) {
    const float* x    = (const float*)d_in[0];
    const int*   ei   = (const int*)d_in[1];
    const float* Wl   = (const float*)d_in[2];
    const float* bl   = (const float*)d_in[3];
    const float* Wr   = (const float*)d_in[4];
    const float* br   = (const float*)d_in[5];
    const float* att  = (const float*)d_in[6];
    const float* bias = (const float*)d_in[7];
    const float* Wp   = (const float*)d_in[8];
    const float* bp   = (const float*)d_in[9];
    const float* gam  = (const float*)d_in[10];
    const float* bet  = (const float*)d_in[11];
    float* out = (float*)d_out;

    static cudaStream_t s_side = nullptr;
    static cudaEvent_t ev_fork = nullptr, ev_join = nullptr;
    if (!s_side) {
        cudaStreamCreateWithFlags(&s_side, cudaStreamNonBlocking);
        cudaEventCreateWithFlags(&ev_fork, cudaEventDisableTiming);
        cudaEventCreateWithFlags(&ev_join, cudaEventDisableTiming);
        cudaFuncSetAttribute(k_gemm, cudaFuncAttributeMaxDynamicSharedMemorySize,
                             GEMM_SMEM);
        cudaFuncSetAttribute(k_proj, cudaFuncAttributeMaxDynamicSharedMemorySize,
                             PROJ_SMEM);
    }

    // fork: tensor-core GEMM on side overlaps CSR build on main
    cudaEventRecord(ev_fork, 0);
    cudaStreamWaitEvent(s_side, ev_fork, 0);
    k_gemm<<<(MROWS + 127) / 128, 256, GEMM_SMEM, s_side>>>(x, Wl, bl, Wr, br);
    cudaEventRecord(ev_join, s_side);

    k_hist<<<(EE / 4 + 255) / 256, 256>>>(ei);
    k_scan<<<1, 1024>>>();
    k_scatter<<<(EE / 4 + 255) / 256, 256>>>(ei);

    cudaStreamWaitEvent(0, ev_join, 0);
    k_agg<<<(NN + 7) / 8, 256>>>(att, bias);
    k_proj<<<(MROWS + 63) / 64, 256, PROJ_SMEM>>>(x, Wp, bp, gam, bet, out);
}

// round 13
// speedup vs baseline: 1.0414x; 1.0414x over previous
#include <cuda_runtime.h>
#include <cuda_fp16.h>

#define NN 10000
#define TT 2
#define CC 64
#define HH 4
#define CO 64
#define HC 256
#define EE 160000
#define MROWS (TT*NN)

// scratch (static device allocations; no cudaMalloc allowed)
__device__ __half g_xlh[MROWS * HC];   // x_l in fp16 (gathered tensor)
__device__ float  g_xr[MROWS * HC];
__device__ __half g_mhah[MROWS * HC];  // x_mha in fp16
__device__ int    g_deg[NN];           // zero-initialized; scan re-zeroes after use
__device__ int    g_rowptr[NN + 1];
__device__ int    g_cursor[NN];
__device__ int    g_srcs[EE];
__device__ int    g_histdone;          // completion counter; reset each call

// Fused histogram + prefix scan. 4 edges per thread via int4; the LAST block
// (completion-counter) performs the 256-thread scan over g_deg, writes
// rowptr/cursor, zeroes g_deg and resets the counter (replay-deterministic).
__global__ void k_histscan(const int* __restrict__ ei) {
    int i = blockIdx.x * blockDim.x + threadIdx.x;
    if (i < EE / 4) {
        int4 d4 = ((const int4*)(ei + EE))[i];
        atomicAdd(&g_deg[d4.x], 1);
        atomicAdd(&g_deg[d4.y], 1);
        atomicAdd(&g_deg[d4.z], 1);
        atomicAdd(&g_deg[d4.w], 1);
    }
    __threadfence();
    __shared__ bool isLast;
    if (threadIdx.x == 0) {
        int c = atomicAdd(&g_histdone, 1);
        isLast = (c == gridDim.x - 1);
    }
    __syncthreads();
    if (!isLast) return;

    // ---- scan phase (one block, 256 threads) ----
    __shared__ int sc[256];
    int tid = threadIdx.x;
    const int CH = (NN + 255) / 256;   // 40
    int base = tid * CH;
    int local = 0;
    for (int j = 0; j < CH; j++) {
        int idx = base + j;
        if (idx < NN) local += g_deg[idx];
    }
    sc[tid] = local;
    __syncthreads();
    for (int off = 1; off < 256; off <<= 1) {
        int v = (tid >= off) ? sc[tid - off] : 0;
        __syncthreads();
        sc[tid] += v;
        __syncthreads();
    }
    int run = sc[tid] - local;  // exclusive prefix
    for (int j = 0; j < CH; j++) {
        int idx = base + j;
        if (idx < NN) {
            int d = g_deg[idx];
            g_rowptr[idx] = run;
            g_cursor[idx] = run;
            run += d;
            g_deg[idx] = 0;    // reset for next invocation
        }
    }
    if (tid == 255) {
        g_rowptr[NN] = sc[255];
        g_histdone = 0;        // reset for next invocation
    }
}

__global__ void k_scatter(const int* __restrict__ ei) {
    int i = blockIdx.x * blockDim.x + threadIdx.x;
    if (i < EE / 4) {
        int4 s4 = ((const int4*)ei)[i];
        int4 d4 = ((const int4*)(ei + EE))[i];
        g_srcs[atomicAdd(&g_cursor[d4.x], 1)] = s4.x;
        g_srcs[atomicAdd(&g_cursor[d4.y], 1)] = s4.y;
        g_srcs[atomicAdd(&g_cursor[d4.z], 1)] = s4.z;
        g_srcs[atomicAdd(&g_cursor[d4.w], 1)] = s4.w;
    }
}

// ================= Tensor-core dual GEMM =================
#define XS_STRIDE 72
#define GEMM_SMEM ((128 * XS_STRIDE + 512 * XS_STRIDE) * 2)

__device__ __forceinline__ unsigned ldsm(const __half* p) {
    return *(const unsigned*)p;
}

__device__ __forceinline__ void mma16816(float* d, const unsigned* a,
                                         unsigned b0, unsigned b1) {
    asm volatile(
        "mma.sync.aligned.m16n8k16.row.col.f32.f16.f16.f32 "
        "{%0,%1,%2,%3}, {%4,%5,%6,%7}, {%8,%9}, {%0,%1,%2,%3};\n"
        : "+f"(d[0]), "+f"(d[1]), "+f"(d[2]), "+f"(d[3])
        : "r"(a[0]), "r"(a[1]), "r"(a[2]), "r"(a[3]), "r"(b0), "r"(b1));
}

__global__ void __launch_bounds__(256) k_gemm(
    const float* __restrict__ x,
    const float* __restrict__ Wl, const float* __restrict__ bl,
    const float* __restrict__ Wr, const float* __restrict__ br)
{
    extern __shared__ __half smem[];
    __half* xs = smem;                       // [128][72]
    __half* Wt = smem + 128 * XS_STRIDE;     // [512][72]

    int tid = threadIdx.x;
    int row0 = blockIdx.x * 128;

#pragma unroll
    for (int it = 0; it < 32; it++) {
        int flat = it * 256 + tid;
        int r = flat >> 6, c = flat & 63;
        int grow = row0 + r;
        float v = (grow < MROWS) ? x[grow * CC + c] : 0.f;
        xs[r * XS_STRIDE + c] = __float2half(v);
    }
#pragma unroll
    for (int it = 0; it < 128; it++) {
        int flat = it * 256 + tid;
        int k = flat >> 9, n = flat & 511;
        float v = (n < HC) ? Wl[k * HC + n] : Wr[k * HC + (n - HC)];
        Wt[n * XS_STRIDE + k] = __float2half(v);
    }
    __syncthreads();

    int lane = tid & 31;
    int wid = tid >> 5;
    int g = lane >> 2;
    int q = lane & 3;
    int wm = wid * 16;

    unsigned Areg[4][4];
#pragma unroll
    for (int ks = 0; ks < 4; ks++) {
        int kb = ks * 16 + q * 2;
        Areg[ks][0] = ldsm(&xs[(wm + g) * XS_STRIDE + kb]);
        Areg[ks][1] = ldsm(&xs[(wm + g + 8) * XS_STRIDE + kb]);
        Areg[ks][2] = ldsm(&xs[(wm + g) * XS_STRIDE + kb + 8]);
        Areg[ks][3] = ldsm(&xs[(wm + g + 8) * XS_STRIDE + kb + 8]);
    }

    int row_lo = row0 + wm + g;
    int row_hi = row_lo + 8;

#pragma unroll 1
    for (int chunk = 0; chunk < 8; chunk++) {
        float d[8][4];
#pragma unroll
        for (int nt = 0; nt < 8; nt++)
#pragma unroll
            for (int e = 0; e < 4; e++) d[nt][e] = 0.f;

#pragma unroll
        for (int ks = 0; ks < 4; ks++) {
            int kb = ks * 16 + q * 2;
#pragma unroll
            for (int nt = 0; nt < 8; nt++) {
                int n = chunk * 64 + nt * 8 + g;
                unsigned b0 = ldsm(&Wt[n * XS_STRIDE + kb]);
                unsigned b1 = ldsm(&Wt[n * XS_STRIDE + kb + 8]);
                mma16816(d[nt], Areg[ks], b0, b1);
            }
        }

#pragma unroll
        for (int nt = 0; nt < 8; nt++) {
            int colg = chunk * 64 + nt * 8 + q * 2;
            if (colg < HC) {
                float b0v = bl[colg], b1v = bl[colg + 1];
                if (row_lo < MROWS) {
                    __half2 h = __floats2half2_rn(d[nt][0] + b0v, d[nt][1] + b1v);
                    *(__half2*)&g_xlh[row_lo * HC + colg] = h;
                }
                if (row_hi < MROWS) {
                    __half2 h = __floats2half2_rn(d[nt][2] + b0v, d[nt][3] + b1v);
                    *(__half2*)&g_xlh[row_hi * HC + colg] = h;
                }
            } else {
                int c = colg - HC;
                float b0v = br[c], b1v = br[c + 1];
                if (row_lo < MROWS) {
                    float2 f = make_float2(d[nt][0] + b0v, d[nt][1] + b1v);
                    *(float2*)&g_xr[row_lo * HC + c] = f;
                }
                if (row_hi < MROWS) {
                    float2 f = make_float2(d[nt][2] + b0v, d[nt][3] + b1v);
                    *(float2*)&g_xr[row_hi * HC + c] = f;
                }
            }
        }
    }
}

// GAT aggregation: one WARP per (t, n). Range [woff, wend) for stream split.
__device__ __forceinline__ int get_src(int k, int s0, int s1, int base) {
    if (k < 32) return __shfl_sync(0xffffffffu, s0, k);
    if (k < 64) return __shfl_sync(0xffffffffu, s1, k - 32);
    return g_srcs[base + k];
}

__device__ __forceinline__ void h2f8(uint4 u, float4& a0, float4& a1) {
    float2 f0 = __half22float2(*(__half2*)&u.x);
    float2 f1 = __half22float2(*(__half2*)&u.y);
    float2 f2 = __half22float2(*(__half2*)&u.z);
    float2 f3 = __half22float2(*(__half2*)&u.w);
    a0 = make_float4(f0.x, f0.y, f1.x, f1.y);
    a1 = make_float4(f2.x, f2.y, f3.x, f3.y);
}

__global__ void __launch_bounds__(256) k_agg(
    const float* __restrict__ att,
    const float* __restrict__ bias,
    int woff, int wend)
{
    int w = woff + blockIdx.x * 8 + (threadIdx.x >> 5);
    if (w >= wend) return;
    int lane = threadIdx.x & 31;
    int n = w % NN;
    int t = w / NN;
    int f4 = lane * 2;

    const float4* xr = (const float4*)&g_xr[w * HC];
    float4 xr0 = xr[f4];
    float4 xr1 = xr[f4 + 1];
    float4 at0 = ((const float4*)att)[f4];
    float4 at1 = ((const float4*)att)[f4 + 1];

    int base = g_rowptr[n];
    int deg = g_rowptr[n + 1] - base;

    int s0 = (lane < deg) ? g_srcs[base + lane] : 0;
    int s1 = (32 + lane < deg) ? g_srcs[base + 32 + lane] : 0;

    float den = 0.f;
    float4 acc0 = make_float4(0.f, 0.f, 0.f, 0.f);
    float4 acc1 = make_float4(0.f, 0.f, 0.f, 0.f);
    const uint4* xlh4 = (const uint4*)g_xlh;
    int xlbase = t * NN * (HC / 8);

    uint4 A, B, C, D;
    if (deg > 0) A = xlh4[xlbase + get_src(0, s0, s1, base) * (HC / 8) + lane];
    if (deg > 1) B = xlh4[xlbase + get_src(1, s0, s1, base) * (HC / 8) + lane];
    if (deg > 2) C = xlh4[xlbase + get_src(2, s0, s1, base) * (HC / 8) + lane];
    if (deg > 3) D = xlh4[xlbase + get_src(3, s0, s1, base) * (HC / 8) + lane];

#define AGG_BODY(u)                                                          \
    {                                                                        \
        float4 a0, a1;                                                       \
        h2f8(u, a0, a1);                                                     \
        float v, p;                                                          \
        v = a0.x + xr0.x; v = fmaxf(v, 0.2f * v); p = v * at0.x;             \
        v = a0.y + xr0.y; v = fmaxf(v, 0.2f * v); p = fmaf(v, at0.y, p);     \
        v = a0.z + xr0.z; v = fmaxf(v, 0.2f * v); p = fmaf(v, at0.z, p);     \
        v = a0.w + xr0.w; v = fmaxf(v, 0.2f * v); p = fmaf(v, at0.w, p);     \
        v = a1.x + xr1.x; v = fmaxf(v, 0.2f * v); p = fmaf(v, at1.x, p);     \
        v = a1.y + xr1.y; v = fmaxf(v, 0.2f * v); p = fmaf(v, at1.y, p);     \
        v = a1.z + xr1.z; v = fmaxf(v, 0.2f * v); p = fmaf(v, at1.z, p);     \
        v = a1.w + xr1.w; v = fmaxf(v, 0.2f * v); p = fmaf(v, at1.w, p);     \
        p += __shfl_xor_sync(0xffffffffu, p, 1);                             \
        p += __shfl_xor_sync(0xffffffffu, p, 2);                             \
        p += __shfl_xor_sync(0xffffffffu, p, 4);                             \
        float e = __expf(p);                                                 \
        den += e;                                                            \
        acc0.x = fmaf(e, a0.x, acc0.x);                                      \
        acc0.y = fmaf(e, a0.y, acc0.y);                                      \
        acc0.z = fmaf(e, a0.z, acc0.z);                                      \
        acc0.w = fmaf(e, a0.w, acc0.w);                                      \
        acc1.x = fmaf(e, a1.x, acc1.x);                                      \
        acc1.y = fmaf(e, a1.y, acc1.y);                                      \
        acc1.z = fmaf(e, a1.z, acc1.z);                                      \
        acc1.w = fmaf(e, a1.w, acc1.w);                                      \
    }

#define AGG_STEP(R)                                                          \
    {                                                                        \
        uint4 u = R;                                                         \
        if (k + 4 < deg)                                                     \
            R = xlh4[xlbase + get_src(k + 4, s0, s1, base) * (HC / 8) + lane]; \
        AGG_BODY(u);                                                         \
        k++;                                                                 \
    }

    int k = 0;
    while (k < deg) {
        AGG_STEP(A);
        if (k >= deg) break;
        AGG_STEP(B);
        if (k >= deg) break;
        AGG_STEP(C);
        if (k >= deg) break;
        AGG_STEP(D);
    }
#undef AGG_STEP
#undef AGG_BODY

    float inv = (deg > 0) ? 1.0f / den : 0.f;
    const float4* b4 = (const float4*)bias;
    float4 bb0 = b4[f4], bb1 = b4[f4 + 1];
    float o0, o1, o2, o3, o4, o5, o6, o7;
    o0 = fmaxf(fmaf(acc0.x, inv, bb0.x), 0.f);
    o1 = fmaxf(fmaf(acc0.y, inv, bb0.y), 0.f);
    o2 = fmaxf(fmaf(acc0.z, inv, bb0.z), 0.f);
    o3 = fmaxf(fmaf(acc0.w, inv, bb0.w), 0.f);
    o4 = fmaxf(fmaf(acc1.x, inv, bb1.x), 0.f);
    o5 = fmaxf(fmaf(acc1.y, inv, bb1.y), 0.f);
    o6 = fmaxf(fmaf(acc1.z, inv, bb1.z), 0.f);
    o7 = fmaxf(fmaf(acc1.w, inv, bb1.w), 0.f);
    __half2 h0 = __floats2half2_rn(o0, o1);
    __half2 h1 = __floats2half2_rn(o2, o3);
    __half2 h2 = __floats2half2_rn(o4, o5);
    __half2 h3 = __floats2half2_rn(o6, o7);
    uint4 pk;
    pk.x = *(unsigned*)&h0; pk.y = *(unsigned*)&h1;
    pk.z = *(unsigned*)&h2; pk.w = *(unsigned*)&h3;
    ((uint4*)g_mhah)[w * (HC / 8) + lane] = pk;
}

// ============ Tensor-core projection + residual + LayerNorm + relu ============
#define PJ_STRIDE 264
#define PROJ_SMEM ((64 * PJ_STRIDE + 64 * PJ_STRIDE) * 2)

__global__ void __launch_bounds__(256) k_proj(
    const float* __restrict__ x,
    const float* __restrict__ Wp, const float* __restrict__ bp,
    const float* __restrict__ gam, const float* __restrict__ bet,
    float* __restrict__ out, int rbase, int rlim)
{
    extern __shared__ __half psm[];
    __half* xs = psm;                      // [64][264]
    __half* Wt = psm + 64 * PJ_STRIDE;     // [64 n][264 k]
    float* ys = (float*)psm;               // [64][68], aliases xs after MMA

    int tid = threadIdx.x;
    int row0 = rbase + blockIdx.x * 64;

    const uint4* src = (const uint4*)g_mhah;
#pragma unroll
    for (int it = 0; it < 8; it++) {
        int flat = it * 256 + tid;
        int r = flat >> 5, u = flat & 31;
        int grow = row0 + r;
        uint4 v = make_uint4(0u, 0u, 0u, 0u);
        if (grow < rlim) v = src[grow * (HC / 8) + u];
        *(uint4*)&xs[r * PJ_STRIDE + u * 8] = v;
    }
#pragma unroll
    for (int it = 0; it < 64; it++) {
        int flat = it * 256 + tid;
        int k = flat >> 6, n = flat & 63;
        Wt[n * PJ_STRIDE + k] = __float2half(Wp[k * CO + n]);
    }
    __syncthreads();

    int lane = tid & 31, wid = tid >> 5;
    int g = lane >> 2, q = lane & 3;
    int wm = (wid & 3) * 16;
    int nh = (wid >> 2) * 32;

    float d[4][4];
#pragma unroll
    for (int nt = 0; nt < 4; nt++)
#pragma unroll
        for (int e = 0; e < 4; e++) d[nt][e] = 0.f;

#pragma unroll 4
    for (int ks = 0; ks < 16; ks++) {
        int kb = ks * 16 + q * 2;
        unsigned a[4];
        a[0] = ldsm(&xs[(wm + g) * PJ_STRIDE + kb]);
        a[1] = ldsm(&xs[(wm + g + 8) * PJ_STRIDE + kb]);
        a[2] = ldsm(&xs[(wm + g) * PJ_STRIDE + kb + 8]);
        a[3] = ldsm(&xs[(wm + g + 8) * PJ_STRIDE + kb + 8]);
#pragma unroll
        for (int nt = 0; nt < 4; nt++) {
            int n = nh + nt * 8 + g;
            unsigned b0 = ldsm(&Wt[n * PJ_STRIDE + kb]);
            unsigned b1 = ldsm(&Wt[n * PJ_STRIDE + kb + 8]);
            mma16816(d[nt], a, b0, b1);
        }
    }
    __syncthreads();

#pragma unroll
    for (int nt = 0; nt < 4; nt++) {
        int c = nh + nt * 8 + q * 2;
        float b0v = bp[c], b1v = bp[c + 1];
        int rl = wm + g, rh = wm + g + 8;
        int gl = row0 + rl, gh = row0 + rh;
        if (gl < rlim) {
            ys[rl * 68 + c]     = d[nt][0] + b0v + x[gl * CC + c];
            ys[rl * 68 + c + 1] = d[nt][1] + b1v + x[gl * CC + c + 1];
        }
        if (gh < rlim) {
            ys[rh * 68 + c]     = d[nt][2] + b0v + x[gh * CC + c];
            ys[rh * 68 + c + 1] = d[nt][3] + b1v + x[gh * CC + c + 1];
        }
    }
    __syncthreads();

    float g0 = gam[lane], g1 = gam[lane + 32];
    float b0 = bet[lane], b1 = bet[lane + 32];
#pragma unroll
    for (int r = 0; r < 8; r++) {
        int row = wid * 8 + r;
        int grow = row0 + row;
        if (grow >= rlim) break;
        float v0 = ys[row * 68 + lane];
        float v1 = ys[row * 68 + lane + 32];
        float sv = v0 + v1;
        float sq = v0 * v0 + v1 * v1;
#pragma unroll
        for (int off = 16; off; off >>= 1) {
            sv += __shfl_xor_sync(0xffffffffu, sv, off);
            sq += __shfl_xor_sync(0xffffffffu, sq, off);
        }
        float mu = sv * (1.f / 64.f);
        float var = sq * (1.f / 64.f) - mu * mu;
        float rstd = rsqrtf(var + 1e-5f);
        float y0 = (v0 - mu) * rstd * g0 + b0;
        float y1 = (v1 - mu) * rstd * g1 + b1;
        out[grow * CC + lane]      = fmaxf(y0, 0.f);
        out[grow * CC + lane + 32] = fmaxf(y1, 0.f);
    }
}

extern "C" void kernel_launch(void* const* d_in, const int* in_sizes, int n_in,
                              void* d_out, int out_size) {
    const float* x    = (const float*)d_in[0];
    const int*   ei   = (const int*)d_in[1];
    const float* Wl   = (const float*)d_in[2];
    const float* bl   = (const float*)d_in[3];
    const float* Wr   = (const float*)d_in[4];
    const float* br   = (const float*)d_in[5];
    const float* att  = (const float*)d_in[6];
    const float* bias = (const float*)d_in[7];
    const float* Wp   = (const float*)d_in[8];
    const float* bp   = (const float*)d_in[9];
    const float* gam  = (const float*)d_in[10];
    const float* bet  = (const float*)d_in[11];
    float* out = (float*)d_out;

    static cudaStream_t s_side = nullptr;
    static cudaEvent_t ev_fork = nullptr, ev_join = nullptr;
    static cudaEvent_t ev_csr = nullptr, ev_done = nullptr;
    if (!s_side) {
        cudaStreamCreateWithFlags(&s_side, cudaStreamNonBlocking);
        cudaEventCreateWithFlags(&ev_fork, cudaEventDisableTiming);
        cudaEventCreateWithFlags(&ev_join, cudaEventDisableTiming);
        cudaEventCreateWithFlags(&ev_csr, cudaEventDisableTiming);
        cudaEventCreateWithFlags(&ev_done, cudaEventDisableTiming);
        cudaFuncSetAttribute(k_gemm, cudaFuncAttributeMaxDynamicSharedMemorySize,
                             GEMM_SMEM);
        cudaFuncSetAttribute(k_proj, cudaFuncAttributeMaxDynamicSharedMemorySize,
                             PROJ_SMEM);
    }

    // fork: tensor-core GEMM on side overlaps CSR build on main
    cudaEventRecord(ev_fork, 0);
    cudaStreamWaitEvent(s_side, ev_fork, 0);
    k_gemm<<<(MROWS + 127) / 128, 256, GEMM_SMEM, s_side>>>(x, Wl, bl, Wr, br);
    cudaEventRecord(ev_join, s_side);

    k_histscan<<<(EE / 4 + 255) / 256, 256>>>(ei);
    k_scatter<<<(EE / 4 + 255) / 256, 256>>>(ei);
    cudaEventRecord(ev_csr, 0);

    // side stream: t=1 half (needs gemm [in-order] + CSR [event])
    cudaStreamWaitEvent(s_side, ev_csr, 0);
    k_agg<<<(NN + 7) / 8, 256, 0, s_side>>>(att, bias, NN, MROWS);
    k_proj<<<(NN + 63) / 64, 256, PROJ_SMEM, s_side>>>(
        x, Wp, bp, gam, bet, out, NN, MROWS);
    cudaEventRecord(ev_done, s_side);

    // main stream: t=0 half (needs gemm via ev_join; CSR in-order)
    cudaStreamWaitEvent(0, ev_join, 0);
    k_agg<<<(NN + 7) / 8, 256>>>(att, bias, 0, NN);
    k_proj<<<(NN + 63) / 64, 256, PROJ_SMEM>>>(x, Wp, bp, gam, bet, out, 0, NN);

    cudaStreamWaitEvent(0, ev_done, 0);
}

// round 14
// speedup vs baseline: 1.1534x; 1.1075x over previous
#include <cuda_runtime.h>
#include <cuda_fp16.h>

#define NN 10000
#define TT 2
#define CC 64
#define HH 4
#define CO 64
#define HC 256
#define EE 160000
#define MROWS (TT*NN)

// scratch (static device allocations; no cudaMalloc allowed)
__device__ __half g_xlh[MROWS * HC];   // x_l in fp16 (gathered tensor)
__device__ float  g_xr[MROWS * HC];
__device__ __half g_mhah[MROWS * HC];  // x_mha in fp16
__device__ int    g_deg[NN];           // zero-initialized; k_scan re-zeroes after use
__device__ int    g_rowptr[NN + 1];
__device__ int    g_cursor[NN];
__device__ int    g_srcs[EE];

// 4 edges per thread via int4
__global__ void k_hist(const int* __restrict__ ei) {
    int i = blockIdx.x * blockDim.x + threadIdx.x;
    if (i < EE / 4) {
        int4 d4 = ((const int4*)(ei + EE))[i];
        atomicAdd(&g_deg[d4.x], 1);
        atomicAdd(&g_deg[d4.y], 1);
        atomicAdd(&g_deg[d4.z], 1);
        atomicAdd(&g_deg[d4.w], 1);
    }
}

__global__ void __launch_bounds__(1024) k_scan() {
    __shared__ int sc[1024];
    int tid = threadIdx.x;
    const int CH = (NN + 1023) / 1024;  // 10
    int base = tid * CH;
    int local = 0;
    for (int j = 0; j < CH; j++) {
        int idx = base + j;
        if (idx < NN) local += g_deg[idx];
    }
    sc[tid] = local;
    __syncthreads();
    for (int off = 1; off < 1024; off <<= 1) {
        int v = (tid >= off) ? sc[tid - off] : 0;
        __syncthreads();
        sc[tid] += v;
        __syncthreads();
    }
    int run = sc[tid] - local;  // exclusive prefix
    for (int j = 0; j < CH; j++) {
        int idx = base + j;
        if (idx < NN) {
            int d = g_deg[idx];
            g_rowptr[idx] = run;
            g_cursor[idx] = run;
            run += d;
            g_deg[idx] = 0;   // reset for next invocation (replay-deterministic)
        }
    }
    if (tid == 1023) g_rowptr[NN] = sc[1023];
}

__global__ void k_scatter(const int* __restrict__ ei) {
    int i = blockIdx.x * blockDim.x + threadIdx.x;
    if (i < EE / 4) {
        int4 s4 = ((const int4*)ei)[i];
        int4 d4 = ((const int4*)(ei + EE))[i];
        g_srcs[atomicAdd(&g_cursor[d4.x], 1)] = s4.x;
        g_srcs[atomicAdd(&g_cursor[d4.y], 1)] = s4.y;
        g_srcs[atomicAdd(&g_cursor[d4.z], 1)] = s4.z;
        g_srcs[atomicAdd(&g_cursor[d4.w], 1)] = s4.w;
    }
}

// ================= Tensor-core dual GEMM =================
#define XS_STRIDE 72
#define GEMM_SMEM ((128 * XS_STRIDE + 512 * XS_STRIDE) * 2)

__device__ __forceinline__ unsigned ldsm(const __half* p) {
    return *(const unsigned*)p;
}

__device__ __forceinline__ void mma16816(float* d, const unsigned* a,
                                         unsigned b0, unsigned b1) {
    asm volatile(
        "mma.sync.aligned.m16n8k16.row.col.f32.f16.f16.f32 "
        "{%0,%1,%2,%3}, {%4,%5,%6,%7}, {%8,%9}, {%0,%1,%2,%3};\n"
        : "+f"(d[0]), "+f"(d[1]), "+f"(d[2]), "+f"(d[3])
        : "r"(a[0]), "r"(a[1]), "r"(a[2]), "r"(a[3]), "r"(b0), "r"(b1));
}

__global__ void __launch_bounds__(256) k_gemm(
    const float* __restrict__ x,
    const float* __restrict__ Wl, const float* __restrict__ bl,
    const float* __restrict__ Wr, const float* __restrict__ br)
{
    extern __shared__ __half smem[];
    __half* xs = smem;                       // [128][72]
    __half* Wt = smem + 128 * XS_STRIDE;     // [512][72]

    int tid = threadIdx.x;
    int row0 = blockIdx.x * 128;

#pragma unroll
    for (int it = 0; it < 32; it++) {
        int flat = it * 256 + tid;
        int r = flat >> 6, c = flat & 63;
        int grow = row0 + r;
        float v = (grow < MROWS) ? x[grow * CC + c] : 0.f;
        xs[r * XS_STRIDE + c] = __float2half(v);
    }
#pragma unroll
    for (int it = 0; it < 128; it++) {
        int flat = it * 256 + tid;
        int k = flat >> 9, n = flat & 511;
        float v = (n < HC) ? Wl[k * HC + n] : Wr[k * HC + (n - HC)];
        Wt[n * XS_STRIDE + k] = __float2half(v);
    }
    __syncthreads();

    int lane = tid & 31;
    int wid = tid >> 5;
    int g = lane >> 2;
    int q = lane & 3;
    int wm = wid * 16;

    unsigned Areg[4][4];
#pragma unroll
    for (int ks = 0; ks < 4; ks++) {
        int kb = ks * 16 + q * 2;
        Areg[ks][0] = ldsm(&xs[(wm + g) * XS_STRIDE + kb]);
        Areg[ks][1] = ldsm(&xs[(wm + g + 8) * XS_STRIDE + kb]);
        Areg[ks][2] = ldsm(&xs[(wm + g) * XS_STRIDE + kb + 8]);
        Areg[ks][3] = ldsm(&xs[(wm + g + 8) * XS_STRIDE + kb + 8]);
    }

    int row_lo = row0 + wm + g;
    int row_hi = row_lo + 8;

#pragma unroll 1
    for (int chunk = 0; chunk < 8; chunk++) {
        float d[8][4];
#pragma unroll
        for (int nt = 0; nt < 8; nt++)
#pragma unroll
            for (int e = 0; e < 4; e++) d[nt][e] = 0.f;

#pragma unroll
        for (int ks = 0; ks < 4; ks++) {
            int kb = ks * 16 + q * 2;
#pragma unroll
            for (int nt = 0; nt < 8; nt++) {
                int n = chunk * 64 + nt * 8 + g;
                unsigned b0 = ldsm(&Wt[n * XS_STRIDE + kb]);
                unsigned b1 = ldsm(&Wt[n * XS_STRIDE + kb + 8]);
                mma16816(d[nt], Areg[ks], b0, b1);
            }
        }

#pragma unroll
        for (int nt = 0; nt < 8; nt++) {
            int colg = chunk * 64 + nt * 8 + q * 2;
            if (colg < HC) {
                float b0v = bl[colg], b1v = bl[colg + 1];
                if (row_lo < MROWS) {
                    __half2 h = __floats2half2_rn(d[nt][0] + b0v, d[nt][1] + b1v);
                    *(__half2*)&g_xlh[row_lo * HC + colg] = h;
                }
                if (row_hi < MROWS) {
                    __half2 h = __floats2half2_rn(d[nt][2] + b0v, d[nt][3] + b1v);
                    *(__half2*)&g_xlh[row_hi * HC + colg] = h;
                }
            } else {
                int c = colg - HC;
                float b0v = br[c], b1v = br[c + 1];
                if (row_lo < MROWS) {
                    float2 f = make_float2(d[nt][0] + b0v, d[nt][1] + b1v);
                    *(float2*)&g_xr[row_lo * HC + c] = f;
                }
                if (row_hi < MROWS) {
                    float2 f = make_float2(d[nt][2] + b0v, d[nt][3] + b1v);
                    *(float2*)&g_xr[row_hi * HC + c] = f;
                }
            }
        }
    }
}

// GAT aggregation: one WARP per (t, n). Range [woff, wend) for stream split.
// Alpha path in packed half2 (HADD2/HMUL2/HMAX2/HFMA2); accumulation exact fp32.
__device__ __forceinline__ int get_src(int k, int s0, int s1, int base) {
    if (k < 32) return __shfl_sync(0xffffffffu, s0, k);
    if (k < 64) return __shfl_sync(0xffffffffu, s1, k - 32);
    return g_srcs[base + k];
}

__global__ void __launch_bounds__(256) k_agg(
    const float* __restrict__ att,
    const float* __restrict__ bias,
    int woff, int wend)
{
    int w = woff + blockIdx.x * 8 + (threadIdx.x >> 5);
    if (w >= wend) return;
    int lane = threadIdx.x & 31;
    int n = w % NN;
    int t = w / NN;
    int f4 = lane * 2;

    // preconvert xr and att to half2 (once per warp-node; alpha path is fp16)
    const float4* xr = (const float4*)&g_xr[w * HC];
    float4 xrf0 = xr[f4];
    float4 xrf1 = xr[f4 + 1];
    float4 atf0 = ((const float4*)att)[f4];
    float4 atf1 = ((const float4*)att)[f4 + 1];
    __half2 xh0 = __floats2half2_rn(xrf0.x, xrf0.y);
    __half2 xh1 = __floats2half2_rn(xrf0.z, xrf0.w);
    __half2 xh2 = __floats2half2_rn(xrf1.x, xrf1.y);
    __half2 xh3 = __floats2half2_rn(xrf1.z, xrf1.w);
    __half2 ah0 = __floats2half2_rn(atf0.x, atf0.y);
    __half2 ah1 = __floats2half2_rn(atf0.z, atf0.w);
    __half2 ah2 = __floats2half2_rn(atf1.x, atf1.y);
    __half2 ah3 = __floats2half2_rn(atf1.z, atf1.w);
    const __half2 c02 = __float2half2_rn(0.2f);

    int base = g_rowptr[n];
    int deg = g_rowptr[n + 1] - base;

    int s0 = (lane < deg) ? g_srcs[base + lane] : 0;
    int s1 = (32 + lane < deg) ? g_srcs[base + 32 + lane] : 0;

    float den = 0.f;
    float4 acc0 = make_float4(0.f, 0.f, 0.f, 0.f);
    float4 acc1 = make_float4(0.f, 0.f, 0.f, 0.f);
    const uint4* xlh4 = (const uint4*)g_xlh;
    int xlbase = t * NN * (HC / 8);

    uint4 A, B, C, D;
    if (deg > 0) A = xlh4[xlbase + get_src(0, s0, s1, base) * (HC / 8) + lane];
    if (deg > 1) B = xlh4[xlbase + get_src(1, s0, s1, base) * (HC / 8) + lane];
    if (deg > 2) C = xlh4[xlbase + get_src(2, s0, s1, base) * (HC / 8) + lane];
    if (deg > 3) D = xlh4[xlbase + get_src(3, s0, s1, base) * (HC / 8) + lane];

#define AGG_BODY(u)                                                          \
    {                                                                        \
        __half2 q0 = *(__half2*)&u.x, q1 = *(__half2*)&u.y;                  \
        __half2 q2 = *(__half2*)&u.z, q3 = *(__half2*)&u.w;                  \
        __half2 v0 = __hadd2(q0, xh0), v1 = __hadd2(q1, xh1);                \
        __half2 v2 = __hadd2(q2, xh2), v3 = __hadd2(q3, xh3);                \
        v0 = __hmax2(v0, __hmul2(v0, c02));                                  \
        v1 = __hmax2(v1, __hmul2(v1, c02));                                  \
        v2 = __hmax2(v2, __hmul2(v2, c02));                                  \
        v3 = __hmax2(v3, __hmul2(v3, c02));                                  \
        __half2 p2 = __hmul2(v0, ah0);                                       \
        p2 = __hfma2(v1, ah1, p2);                                           \
        p2 = __hfma2(v2, ah2, p2);                                           \
        p2 = __hfma2(v3, ah3, p2);                                           \
        float2 pf = __half22float2(p2);                                      \
        float p = pf.x + pf.y;                                               \
        p += __shfl_xor_sync(0xffffffffu, p, 1);                             \
        p += __shfl_xor_sync(0xffffffffu, p, 2);                             \
        p += __shfl_xor_sync(0xffffffffu, p, 4);                             \
        float e = __expf(p);                                                 \
        den += e;                                                            \
        float2 f0 = __half22float2(q0), f1 = __half22float2(q1);             \
        float2 f2 = __half22float2(q2), f3 = __half22float2(q3);             \
        acc0.x = fmaf(e, f0.x, acc0.x);                                      \
        acc0.y = fmaf(e, f0.y, acc0.y);                                      \
        acc0.z = fmaf(e, f1.x, acc0.z);                                      \
        acc0.w = fmaf(e, f1.y, acc0.w);                                      \
        acc1.x = fmaf(e, f2.x, acc1.x);                                      \
        acc1.y = fmaf(e, f2.y, acc1.y);                                      \
        acc1.z = fmaf(e, f3.x, acc1.z);                                      \
        acc1.w = fmaf(e, f3.y, acc1.w);                                      \
    }

#define AGG_STEP(R)                                                          \
    {                                                                        \
        uint4 u = R;                                                         \
        if (k + 4 < deg)                                                     \
            R = xlh4[xlbase + get_src(k + 4, s0, s1, base) * (HC / 8) + lane]; \
        AGG_BODY(u);                                                         \
        k++;                                                                 \
    }

    int k = 0;
    while (k < deg) {
        AGG_STEP(A);
        if (k >= deg) break;
        AGG_STEP(B);
        if (k >= deg) break;
        AGG_STEP(C);
        if (k >= deg) break;
        AGG_STEP(D);
    }
#undef AGG_STEP
#undef AGG_BODY

    float inv = (deg > 0) ? 1.0f / den : 0.f;
    const float4* b4 = (const float4*)bias;
    float4 bb0 = b4[f4], bb1 = b4[f4 + 1];
    float o0, o1, o2, o3, o4, o5, o6, o7;
    o0 = fmaxf(fmaf(acc0.x, inv, bb0.x), 0.f);
    o1 = fmaxf(fmaf(acc0.y, inv, bb0.y), 0.f);
    o2 = fmaxf(fmaf(acc0.z, inv, bb0.z), 0.f);
    o3 = fmaxf(fmaf(acc0.w, inv, bb0.w), 0.f);
    o4 = fmaxf(fmaf(acc1.x, inv, bb1.x), 0.f);
    o5 = fmaxf(fmaf(acc1.y, inv, bb1.y), 0.f);
    o6 = fmaxf(fmaf(acc1.z, inv, bb1.z), 0.f);
    o7 = fmaxf(fmaf(acc1.w, inv, bb1.w), 0.f);
    __half2 h0 = __floats2half2_rn(o0, o1);
    __half2 h1 = __floats2half2_rn(o2, o3);
    __half2 h2 = __floats2half2_rn(o4, o5);
    __half2 h3 = __floats2half2_rn(o6, o7);
    uint4 pk;
    pk.x = *(unsigned*)&h0; pk.y = *(unsigned*)&h1;
    pk.z = *(unsigned*)&h2; pk.w = *(unsigned*)&h3;
    ((uint4*)g_mhah)[w * (HC / 8) + lane] = pk;
}

// ============ Tensor-core projection + residual + LayerNorm + relu ============
#define PJ_STRIDE 264
#define PROJ_SMEM ((64 * PJ_STRIDE + 64 * PJ_STRIDE) * 2)

__global__ void __launch_bounds__(256) k_proj(
    const float* __restrict__ x,
    const float* __restrict__ Wp, const float* __restrict__ bp,
    const float* __restrict__ gam, const float* __restrict__ bet,
    float* __restrict__ out, int rbase, int rlim)
{
    extern __shared__ __half psm[];
    __half* xs = psm;                      // [64][264]
    __half* Wt = psm + 64 * PJ_STRIDE;     // [64 n][264 k]
    float* ys = (float*)psm;               // [64][68], aliases xs after MMA

    int tid = threadIdx.x;
    int row0 = rbase + blockIdx.x * 64;

    const uint4* src = (const uint4*)g_mhah;
#pragma unroll
    for (int it = 0; it < 8; it++) {
        int flat = it * 256 + tid;
        int r = flat >> 5, u = flat & 31;
        int grow = row0 + r;
        uint4 v = make_uint4(0u, 0u, 0u, 0u);
        if (grow < rlim) v = src[grow * (HC / 8) + u];
        *(uint4*)&xs[r * PJ_STRIDE + u * 8] = v;
    }
#pragma unroll
    for (int it = 0; it < 64; it++) {
        int flat = it * 256 + tid;
        int k = flat >> 6, n = flat & 63;
        Wt[n * PJ_STRIDE + k] = __float2half(Wp[k * CO + n]);
    }
    __syncthreads();

    int lane = tid & 31, wid = tid >> 5;
    int g = lane >> 2, q = lane & 3;
    int wm = (wid & 3) * 16;
    int nh = (wid >> 2) * 32;

    float d[4][4];
#pragma unroll
    for (int nt = 0; nt < 4; nt++)
#pragma unroll
        for (int e = 0; e < 4; e++) d[nt][e] = 0.f;

#pragma unroll 4
    for (int ks = 0; ks < 16; ks++) {
        int kb = ks * 16 + q * 2;
        unsigned a[4];
        a[0] = ldsm(&xs[(wm + g) * PJ_STRIDE + kb]);
        a[1] = ldsm(&xs[(wm + g + 8) * PJ_STRIDE + kb]);
        a[2] = ldsm(&xs[(wm + g) * PJ_STRIDE + kb + 8]);
        a[3] = ldsm(&xs[(wm + g + 8) * PJ_STRIDE + kb + 8]);
#pragma unroll
        for (int nt = 0; nt < 4; nt++) {
            int n = nh + nt * 8 + g;
            unsigned b0 = ldsm(&Wt[n * PJ_STRIDE + kb]);
            unsigned b1 = ldsm(&Wt[n * PJ_STRIDE + kb + 8]);
            mma16816(d[nt], a, b0, b1);
        }
    }
    __syncthreads();

#pragma unroll
    for (int nt = 0; nt < 4; nt++) {
        int c = nh + nt * 8 + q * 2;
        float b0v = bp[c], b1v = bp[c + 1];
        int rl = wm + g, rh = wm + g + 8;
        int gl = row0 + rl, gh = row0 + rh;
        if (gl < rlim) {
            ys[rl * 68 + c]     = d[nt][0] + b0v + x[gl * CC + c];
            ys[rl * 68 + c + 1] = d[nt][1] + b1v + x[gl * CC + c + 1];
        }
        if (gh < rlim) {
            ys[rh * 68 + c]     = d[nt][2] + b0v + x[gh * CC + c];
            ys[rh * 68 + c + 1] = d[nt][3] + b1v + x[gh * CC + c + 1];
        }
    }
    __syncthreads();

    float g0 = gam[lane], g1 = gam[lane + 32];
    float b0 = bet[lane], b1 = bet[lane + 32];
#pragma unroll
    for (int r = 0; r < 8; r++) {
        int row = wid * 8 + r;
        int grow = row0 + row;
        if (grow >= rlim) break;
        float v0 = ys[row * 68 + lane];
        float v1 = ys[row * 68 + lane + 32];
        float sv = v0 + v1;
        float sq = v0 * v0 + v1 * v1;
#pragma unroll
        for (int off = 16; off; off >>= 1) {
            sv += __shfl_xor_sync(0xffffffffu, sv, off);
            sq += __shfl_xor_sync(0xffffffffu, sq, off);
        }
        float mu = sv * (1.f / 64.f);
        float var = sq * (1.f / 64.f) - mu * mu;
        float rstd = rsqrtf(var + 1e-5f);
        float y0 = (v0 - mu) * rstd * g0 + b0;
        float y1 = (v1 - mu) * rstd * g1 + b1;
        out[grow * CC + lane]      = fmaxf(y0, 0.f);
        out[grow * CC + lane + 32] = fmaxf(y1, 0.f);
    }
}

extern "C" void kernel_launch(void* const* d_in, const int* in_sizes, int n_in,
                              void* d_out, int out_size) {
    const float* x    = (const float*)d_in[0];
    const int*   ei   = (const int*)d_in[1];
    const float* Wl   = (const float*)d_in[2];
    const float* bl   = (const float*)d_in[3];
    const float* Wr   = (const float*)d_in[4];
    const float* br   = (const float*)d_in[5];
    const float* att  = (const float*)d_in[6];
    const float* bias = (const float*)d_in[7];
    const float* Wp   = (const float*)d_in[8];
    const float* bp   = (const float*)d_in[9];
    const float* gam  = (const float*)d_in[10];
    const float* bet  = (const float*)d_in[11];
    float* out = (float*)d_out;

    static cudaStream_t s_side = nullptr;
    static cudaEvent_t ev_fork = nullptr, ev_join = nullptr;
    static cudaEvent_t ev_csr = nullptr, ev_done = nullptr;
    if (!s_side) {
        cudaStreamCreateWithFlags(&s_side, cudaStreamNonBlocking);
        cudaEventCreateWithFlags(&ev_fork, cudaEventDisableTiming);
        cudaEventCreateWithFlags(&ev_join, cudaEventDisableTiming);
        cudaEventCreateWithFlags(&ev_csr, cudaEventDisableTiming);
        cudaEventCreateWithFlags(&ev_done, cudaEventDisableTiming);
        cudaFuncSetAttribute(k_gemm, cudaFuncAttributeMaxDynamicSharedMemorySize,
                             GEMM_SMEM);
        cudaFuncSetAttribute(k_proj, cudaFuncAttributeMaxDynamicSharedMemorySize,
                             PROJ_SMEM);
    }

    // fork: tensor-core GEMM on side overlaps CSR build on main
    cudaEventRecord(ev_fork, 0);
    cudaStreamWaitEvent(s_side, ev_fork, 0);
    k_gemm<<<(MROWS + 127) / 128, 256, GEMM_SMEM, s_side>>>(x, Wl, bl, Wr, br);
    cudaEventRecord(ev_join, s_side);

    k_hist<<<(EE / 4 + 255) / 256, 256>>>(ei);
    k_scan<<<1, 1024>>>();
    k_scatter<<<(EE / 4 + 255) / 256, 256>>>(ei);
    cudaEventRecord(ev_csr, 0);

    // side stream: t=1 half (needs gemm [in-order] + CSR [event])
    cudaStreamWaitEvent(s_side, ev_csr, 0);
    k_agg<<<(NN + 7) / 8, 256, 0, s_side>>>(att, bias, NN, MROWS);
    k_proj<<<(NN + 63) / 64, 256, PROJ_SMEM, s_side>>>(
        x, Wp, bp, gam, bet, out, NN, MROWS);
    cudaEventRecord(ev_done, s_side);

    // main stream: t=0 half (needs gemm via ev_join; CSR in-order)
    cudaStreamWaitEvent(0, ev_join, 0);
    k_agg<<<(NN + 7) / 8, 256>>>(att, bias, 0, NN);
    k_proj<<<(NN + 63) / 64, 256, PROJ_SMEM>>>(x, Wp, bp, gam, bet, out, 0, NN);

    cudaStreamWaitEvent(0, ev_done, 0);
}

// round 15
// speedup vs baseline: 1.2381x; 1.0735x over previous
#include <cuda_runtime.h>
#include <cuda_fp16.h>

#define NN 10000
#define TT 2
#define CC 64
#define HH 4
#define CO 64
#define HC 256
#define EE 160000
#define MROWS (TT*NN)

// scratch (static device allocations; no cudaMalloc allowed)
__device__ __half g_xlh[MROWS * HC];   // x_l in fp16 (gathered tensor)
__device__ float  g_xr[MROWS * HC];
__device__ __half g_mhah[MROWS * HC];  // x_mha in fp16
__device__ int    g_deg[NN];           // zero-initialized; k_scan re-zeroes after use
__device__ int    g_rowptr[NN + 1];
__device__ int    g_rank[EE];          // per-edge rank within its dst bucket
__device__ int    g_srcs[EE];

// hist: 4 edges per thread; atomicAdd return value IS the edge's rank.
__global__ void k_hist(const int* __restrict__ ei) {
    int i = blockIdx.x * blockDim.x + threadIdx.x;
    if (i < EE / 4) {
        int4 d4 = ((const int4*)(ei + EE))[i];
        int4 r4;
        r4.x = atomicAdd(&g_deg[d4.x], 1);
        r4.y = atomicAdd(&g_deg[d4.y], 1);
        r4.z = atomicAdd(&g_deg[d4.z], 1);
        r4.w = atomicAdd(&g_deg[d4.w], 1);
        ((int4*)g_rank)[i] = r4;
    }
}

__global__ void __launch_bounds__(1024) k_scan() {
    __shared__ int sc[1024];
    int tid = threadIdx.x;
    const int CH = (NN + 1023) / 1024;  // 10
    int base = tid * CH;
    int local = 0;
    for (int j = 0; j < CH; j++) {
        int idx = base + j;
        if (idx < NN) local += g_deg[idx];
    }
    sc[tid] = local;
    __syncthreads();
    for (int off = 1; off < 1024; off <<= 1) {
        int v = (tid >= off) ? sc[tid - off] : 0;
        __syncthreads();
        sc[tid] += v;
        __syncthreads();
    }
    int run = sc[tid] - local;  // exclusive prefix
    for (int j = 0; j < CH; j++) {
        int idx = base + j;
        if (idx < NN) {
            int d = g_deg[idx];
            g_rowptr[idx] = run;
            run += d;
            g_deg[idx] = 0;   // reset for next invocation (replay-deterministic)
        }
    }
    if (tid == 1023) g_rowptr[NN] = sc[1023];
}

// scatter: NO atomics — pos = rowptr[dst] + rank (precomputed in hist).
__global__ void k_scatter(const int* __restrict__ ei) {
    int i = blockIdx.x * blockDim.x + threadIdx.x;
    if (i < EE / 4) {
        int4 s4 = ((const int4*)ei)[i];
        int4 d4 = ((const int4*)(ei + EE))[i];
        int4 r4 = ((const int4*)g_rank)[i];
        g_srcs[g_rowptr[d4.x] + r4.x] = s4.x;
        g_srcs[g_rowptr[d4.y] + r4.y] = s4.y;
        g_srcs[g_rowptr[d4.z] + r4.z] = s4.z;
        g_srcs[g_rowptr[d4.w] + r4.w] = s4.w;
    }
}

// ================= Tensor-core dual GEMM =================
#define XS_STRIDE 72
#define GEMM_SMEM ((128 * XS_STRIDE + 512 * XS_STRIDE) * 2)

__device__ __forceinline__ unsigned ldsm(const __half* p) {
    return *(const unsigned*)p;
}

__device__ __forceinline__ void mma16816(float* d, const unsigned* a,
                                         unsigned b0, unsigned b1) {
    asm volatile(
        "mma.sync.aligned.m16n8k16.row.col.f32.f16.f16.f32 "
        "{%0,%1,%2,%3}, {%4,%5,%6,%7}, {%8,%9}, {%0,%1,%2,%3};\n"
        : "+f"(d[0]), "+f"(d[1]), "+f"(d[2]), "+f"(d[3])
        : "r"(a[0]), "r"(a[1]), "r"(a[2]), "r"(a[3]), "r"(b0), "r"(b1));
}

__global__ void __launch_bounds__(256) k_gemm(
    const float* __restrict__ x,
    const float* __restrict__ Wl, const float* __restrict__ bl,
    const float* __restrict__ Wr, const float* __restrict__ br)
{
    extern __shared__ __half smem[];
    __half* xs = smem;                       // [128][72]
    __half* Wt = smem + 128 * XS_STRIDE;     // [512][72]

    int tid = threadIdx.x;
    int row0 = blockIdx.x * 128;

#pragma unroll
    for (int it = 0; it < 32; it++) {
        int flat = it * 256 + tid;
        int r = flat >> 6, c = flat & 63;
        int grow = row0 + r;
        float v = (grow < MROWS) ? x[grow * CC + c] : 0.f;
        xs[r * XS_STRIDE + c] = __float2half(v);
    }
#pragma unroll
    for (int it = 0; it < 128; it++) {
        int flat = it * 256 + tid;
        int k = flat >> 9, n = flat & 511;
        float v = (n < HC) ? Wl[k * HC + n] : Wr[k * HC + (n - HC)];
        Wt[n * XS_STRIDE + k] = __float2half(v);
    }
    __syncthreads();

    int lane = tid & 31;
    int wid = tid >> 5;
    int g = lane >> 2;
    int q = lane & 3;
    int wm = wid * 16;

    unsigned Areg[4][4];
#pragma unroll
    for (int ks = 0; ks < 4; ks++) {
        int kb = ks * 16 + q * 2;
        Areg[ks][0] = ldsm(&xs[(wm + g) * XS_STRIDE + kb]);
        Areg[ks][1] = ldsm(&xs[(wm + g + 8) * XS_STRIDE + kb]);
        Areg[ks][2] = ldsm(&xs[(wm + g) * XS_STRIDE + kb + 8]);
        Areg[ks][3] = ldsm(&xs[(wm + g + 8) * XS_STRIDE + kb + 8]);
    }

    int row_lo = row0 + wm + g;
    int row_hi = row_lo + 8;

#pragma unroll 1
    for (int chunk = 0; chunk < 8; chunk++) {
        float d[8][4];
#pragma unroll
        for (int nt = 0; nt < 8; nt++)
#pragma unroll
            for (int e = 0; e < 4; e++) d[nt][e] = 0.f;

#pragma unroll
        for (int ks = 0; ks < 4; ks++) {
            int kb = ks * 16 + q * 2;
#pragma unroll
            for (int nt = 0; nt < 8; nt++) {
                int n = chunk * 64 + nt * 8 + g;
                unsigned b0 = ldsm(&Wt[n * XS_STRIDE + kb]);
                unsigned b1 = ldsm(&Wt[n * XS_STRIDE + kb + 8]);
                mma16816(d[nt], Areg[ks], b0, b1);
            }
        }

#pragma unroll
        for (int nt = 0; nt < 8; nt++) {
            int colg = chunk * 64 + nt * 8 + q * 2;
            if (colg < HC) {
                float b0v = bl[colg], b1v = bl[colg + 1];
                if (row_lo < MROWS) {
                    __half2 h = __floats2half2_rn(d[nt][0] + b0v, d[nt][1] + b1v);
                    *(__half2*)&g_xlh[row_lo * HC + colg] = h;
                }
                if (row_hi < MROWS) {
                    __half2 h = __floats2half2_rn(d[nt][2] + b0v, d[nt][3] + b1v);
                    *(__half2*)&g_xlh[row_hi * HC + colg] = h;
                }
            } else {
                int c = colg - HC;
                float b0v = br[c], b1v = br[c + 1];
                if (row_lo < MROWS) {
                    float2 f = make_float2(d[nt][0] + b0v, d[nt][1] + b1v);
                    *(float2*)&g_xr[row_lo * HC + c] = f;
                }
                if (row_hi < MROWS) {
                    float2 f = make_float2(d[nt][2] + b0v, d[nt][3] + b1v);
                    *(float2*)&g_xr[row_hi * HC + c] = f;
                }
            }
        }
    }
}

// GAT aggregation: one WARP per (t, n). Range [woff, wend) for stream split.
// Alpha path in packed half2 (HADD2/HMUL2/HMAX2/HFMA2); accumulation exact fp32.
__device__ __forceinline__ int get_src(int k, int s0, int s1, int base) {
    if (k < 32) return __shfl_sync(0xffffffffu, s0, k);
    if (k < 64) return __shfl_sync(0xffffffffu, s1, k - 32);
    return g_srcs[base + k];
}

__global__ void __launch_bounds__(256) k_agg(
    const float* __restrict__ att,
    const float* __restrict__ bias,
    int woff, int wend)
{
    int w = woff + blockIdx.x * 8 + (threadIdx.x >> 5);
    if (w >= wend) return;
    int lane = threadIdx.x & 31;
    int n = w % NN;
    int t = w / NN;
    int f4 = lane * 2;

    // preconvert xr and att to half2 (once per warp-node; alpha path is fp16)
    const float4* xr = (const float4*)&g_xr[w * HC];
    float4 xrf0 = xr[f4];
    float4 xrf1 = xr[f4 + 1];
    float4 atf0 = ((const float4*)att)[f4];
    float4 atf1 = ((const float4*)att)[f4 + 1];
    __half2 xh0 = __floats2half2_rn(xrf0.x, xrf0.y);
    __half2 xh1 = __floats2half2_rn(xrf0.z, xrf0.w);
    __half2 xh2 = __floats2half2_rn(xrf1.x, xrf1.y);
    __half2 xh3 = __floats2half2_rn(xrf1.z, xrf1.w);
    __half2 ah0 = __floats2half2_rn(atf0.x, atf0.y);
    __half2 ah1 = __floats2half2_rn(atf0.z, atf0.w);
    __half2 ah2 = __floats2half2_rn(atf1.x, atf1.y);
    __half2 ah3 = __floats2half2_rn(atf1.z, atf1.w);
    const __half2 c02 = __float2half2_rn(0.2f);

    int base = g_rowptr[n];
    int deg = g_rowptr[n + 1] - base;

    int s0 = (lane < deg) ? g_srcs[base + lane] : 0;
    int s1 = (32 + lane < deg) ? g_srcs[base + 32 + lane] : 0;

    float den = 0.f;
    float4 acc0 = make_float4(0.f, 0.f, 0.f, 0.f);
    float4 acc1 = make_float4(0.f, 0.f, 0.f, 0.f);
    const uint4* xlh4 = (const uint4*)g_xlh;
    int xlbase = t * NN * (HC / 8);

    uint4 A, B, C, D;
    if (deg > 0) A = xlh4[xlbase + get_src(0, s0, s1, base) * (HC / 8) + lane];
    if (deg > 1) B = xlh4[xlbase + get_src(1, s0, s1, base) * (HC / 8) + lane];
    if (deg > 2) C = xlh4[xlbase + get_src(2, s0, s1, base) * (HC / 8) + lane];
    if (deg > 3) D = xlh4[xlbase + get_src(3, s0, s1, base) * (HC / 8) + lane];

#define AGG_BODY(u)                                                          \
    {                                                                        \
        __half2 q0 = *(__half2*)&u.x, q1 = *(__half2*)&u.y;                  \
        __half2 q2 = *(__half2*)&u.z, q3 = *(__half2*)&u.w;                  \
        __half2 v0 = __hadd2(q0, xh0), v1 = __hadd2(q1, xh1);                \
        __half2 v2 = __hadd2(q2, xh2), v3 = __hadd2(q3, xh3);                \
        v0 = __hmax2(v0, __hmul2(v0, c02));                                  \
        v1 = __hmax2(v1, __hmul2(v1, c02));                                  \
        v2 = __hmax2(v2, __hmul2(v2, c02));                                  \
        v3 = __hmax2(v3, __hmul2(v3, c02));                                  \
        __half2 p2 = __hmul2(v0, ah0);                                       \
        p2 = __hfma2(v1, ah1, p2);                                           \
        p2 = __hfma2(v2, ah2, p2);                                           \
        p2 = __hfma2(v3, ah3, p2);                                           \
        float2 pf = __half22float2(p2);                                      \
        float p = pf.x + pf.y;                                               \
        p += __shfl_xor_sync(0xffffffffu, p, 1);                             \
        p += __shfl_xor_sync(0xffffffffu, p, 2);                             \
        p += __shfl_xor_sync(0xffffffffu, p, 4);                             \
        float e = __expf(p);                                                 \
        den += e;                                                            \
        float2 f0 = __half22float2(q0), f1 = __half22float2(q1);             \
        float2 f2 = __half22float2(q2), f3 = __half22float2(q3);             \
        acc0.x = fmaf(e, f0.x, acc0.x);                                      \
        acc0.y = fmaf(e, f0.y, acc0.y);                                      \
        acc0.z = fmaf(e, f1.x, acc0.z);                                      \
        acc0.w = fmaf(e, f1.y, acc0.w);                                      \
        acc1.x = fmaf(e, f2.x, acc1.x);                                      \
        acc1.y = fmaf(e, f2.y, acc1.y);                                      \
        acc1.z = fmaf(e, f3.x, acc1.z);                                      \
        acc1.w = fmaf(e, f3.y, acc1.w);                                      \
    }

#define AGG_STEP(R)                                                          \
    {                                                                        \
        uint4 u = R;                                                         \
        if (k + 4 < deg)                                                     \
            R = xlh4[xlbase + get_src(k + 4, s0, s1, base) * (HC / 8) + lane]; \
        AGG_BODY(u);                                                         \
        k++;                                                                 \
    }

    int k = 0;
    while (k < deg) {
        AGG_STEP(A);
        if (k >= deg) break;
        AGG_STEP(B);
        if (k >= deg) break;
        AGG_STEP(C);
        if (k >= deg) break;
        AGG_STEP(D);
    }
#undef AGG_STEP
#undef AGG_BODY

    float inv = (deg > 0) ? 1.0f / den : 0.f;
    const float4* b4 = (const float4*)bias;
    float4 bb0 = b4[f4], bb1 = b4[f4 + 1];
    float o0, o1, o2, o3, o4, o5, o6, o7;
    o0 = fmaxf(fmaf(acc0.x, inv, bb0.x), 0.f);
    o1 = fmaxf(fmaf(acc0.y, inv, bb0.y), 0.f);
    o2 = fmaxf(fmaf(acc0.z, inv, bb0.z), 0.f);
    o3 = fmaxf(fmaf(acc0.w, inv, bb0.w), 0.f);
    o4 = fmaxf(fmaf(acc1.x, inv, bb1.x), 0.f);
    o5 = fmaxf(fmaf(acc1.y, inv, bb1.y), 0.f);
    o6 = fmaxf(fmaf(acc1.z, inv, bb1.z), 0.f);
    o7 = fmaxf(fmaf(acc1.w, inv, bb1.w), 0.f);
    __half2 h0 = __floats2half2_rn(o0, o1);
    __half2 h1 = __floats2half2_rn(o2, o3);
    __half2 h2 = __floats2half2_rn(o4, o5);
    __half2 h3 = __floats2half2_rn(o6, o7);
    uint4 pk;
    pk.x = *(unsigned*)&h0; pk.y = *(unsigned*)&h1;
    pk.z = *(unsigned*)&h2; pk.w = *(unsigned*)&h3;
    ((uint4*)g_mhah)[w * (HC / 8) + lane] = pk;
}

// ============ Tensor-core projection + residual + LayerNorm + relu ============
#define PJ_STRIDE 264
#define PROJ_SMEM ((64 * PJ_STRIDE + 64 * PJ_STRIDE) * 2)

__global__ void __launch_bounds__(256) k_proj(
    const float* __restrict__ x,
    const float* __restrict__ Wp, const float* __restrict__ bp,
    const float* __restrict__ gam, const float* __restrict__ bet,
    float* __restrict__ out, int rbase, int rlim)
{
    extern __shared__ __half psm[];
    __half* xs = psm;                      // [64][264]
    __half* Wt = psm + 64 * PJ_STRIDE;     // [64 n][264 k]
    float* ys = (float*)psm;               // [64][68], aliases xs after MMA

    int tid = threadIdx.x;
    int row0 = rbase + blockIdx.x * 64;

    const uint4* src = (const uint4*)g_mhah;
#pragma unroll
    for (int it = 0; it < 8; it++) {
        int flat = it * 256 + tid;
        int r = flat >> 5, u = flat & 31;
        int grow = row0 + r;
        uint4 v = make_uint4(0u, 0u, 0u, 0u);
        if (grow < rlim) v = src[grow * (HC / 8) + u];
        *(uint4*)&xs[r * PJ_STRIDE + u * 8] = v;
    }
#pragma unroll
    for (int it = 0; it < 64; it++) {
        int flat = it * 256 + tid;
        int k = flat >> 6, n = flat & 63;
        Wt[n * PJ_STRIDE + k] = __float2half(Wp[k * CO + n]);
    }
    __syncthreads();

    int lane = tid & 31, wid = tid >> 5;
    int g = lane >> 2, q = lane & 3;
    int wm = (wid & 3) * 16;
    int nh = (wid >> 2) * 32;

    float d[4][4];
#pragma unroll
    for (int nt = 0; nt < 4; nt++)
#pragma unroll
        for (int e = 0; e < 4; e++) d[nt][e] = 0.f;

#pragma unroll 4
    for (int ks = 0; ks < 16; ks++) {
        int kb = ks * 16 + q * 2;
        unsigned a[4];
        a[0] = ldsm(&xs[(wm + g) * PJ_STRIDE + kb]);
        a[1] = ldsm(&xs[(wm + g + 8) * PJ_STRIDE + kb]);
        a[2] = ldsm(&xs[(wm + g) * PJ_STRIDE + kb + 8]);
        a[3] = ldsm(&xs[(wm + g + 8) * PJ_STRIDE + kb + 8]);
#pragma unroll
        for (int nt = 0; nt < 4; nt++) {
            int n = nh + nt * 8 + g;
            unsigned b0 = ldsm(&Wt[n * PJ_STRIDE + kb]);
            unsigned b1 = ldsm(&Wt[n * PJ_STRIDE + kb + 8]);
            mma16816(d[nt], a, b0, b1);
        }
    }
    __syncthreads();

#pragma unroll
    for (int nt = 0; nt < 4; nt++) {
        int c = nh + nt * 8 + q * 2;
        float b0v = bp[c], b1v = bp[c + 1];
        int rl = wm + g, rh = wm + g + 8;
        int gl = row0 + rl, gh = row0 + rh;
        if (gl < rlim) {
            ys[rl * 68 + c]     = d[nt][0] + b0v + x[gl * CC + c];
            ys[rl * 68 + c + 1] = d[nt][1] + b1v + x[gl * CC + c + 1];
        }
        if (gh < rlim) {
            ys[rh * 68 + c]     = d[nt][2] + b0v + x[gh * CC + c];
            ys[rh * 68 + c + 1] = d[nt][3] + b1v + x[gh * CC + c + 1];
        }
    }
    __syncthreads();

    float g0 = gam[lane], g1 = gam[lane + 32];
    float b0 = bet[lane], b1 = bet[lane + 32];
#pragma unroll
    for (int r = 0; r < 8; r++) {
        int row = wid * 8 + r;
        int grow = row0 + row;
        if (grow >= rlim) break;
        float v0 = ys[row * 68 + lane];
        float v1 = ys[row * 68 + lane + 32];
        float sv = v0 + v1;
        float sq = v0 * v0 + v1 * v1;
#pragma unroll
        for (int off = 16; off; off >>= 1) {
            sv += __shfl_xor_sync(0xffffffffu, sv, off);
            sq += __shfl_xor_sync(0xffffffffu, sq, off);
        }
        float mu = sv * (1.f / 64.f);
        float var = sq * (1.f / 64.f) - mu * mu;
        float rstd = rsqrtf(var + 1e-5f);
        float y0 = (v0 - mu) * rstd * g0 + b0;
        float y1 = (v1 - mu) * rstd * g1 + b1;
        out[grow * CC + lane]      = fmaxf(y0, 0.f);
        out[grow * CC + lane + 32] = fmaxf(y1, 0.f);
    }
}

extern "C" void kernel_launch(void* const* d_in, const int* in_sizes, int n_in,
                              void* d_out, int out_size) {
    const float* x    = (const float*)d_in[0];
    const int*   ei   = (const int*)d_in[1];
    const float* Wl   = (const float*)d_in[2];
    const float* bl   = (const float*)d_in[3];
    const float* Wr   = (const float*)d_in[4];
    const float* br   = (const float*)d_in[5];
    const float* att  = (const float*)d_in[6];
    const float* bias = (const float*)d_in[7];
    const float* Wp   = (const float*)d_in[8];
    const float* bp   = (const float*)d_in[9];
    const float* gam  = (const float*)d_in[10];
    const float* bet  = (const float*)d_in[11];
    float* out = (float*)d_out;

    static cudaStream_t s_side = nullptr;
    static cudaEvent_t ev_fork = nullptr, ev_join = nullptr;
    static cudaEvent_t ev_csr = nullptr, ev_done = nullptr;
    if (!s_side) {
        cudaStreamCreateWithFlags(&s_side, cudaStreamNonBlocking);
        cudaEventCreateWithFlags(&ev_fork, cudaEventDisableTiming);
        cudaEventCreateWithFlags(&ev_join, cudaEventDisableTiming);
        cudaEventCreateWithFlags(&ev_csr, cudaEventDisableTiming);
        cudaEventCreateWithFlags(&ev_done, cudaEventDisableTiming);
        cudaFuncSetAttribute(k_gemm, cudaFuncAttributeMaxDynamicSharedMemorySize,
                             GEMM_SMEM);
        cudaFuncSetAttribute(k_proj, cudaFuncAttributeMaxDynamicSharedMemorySize,
                             PROJ_SMEM);
    }

    // fork: tensor-core GEMM on side overlaps CSR build on main
    cudaEventRecord(ev_fork, 0);
    cudaStreamWaitEvent(s_side, ev_fork, 0);
    k_gemm<<<(MROWS + 127) / 128, 256, GEMM_SMEM, s_side>>>(x, Wl, bl, Wr, br);
    cudaEventRecord(ev_join, s_side);

    k_hist<<<(EE / 4 + 255) / 256, 256>>>(ei);
    k_scan<<<1, 1024>>>();
    k_scatter<<<(EE / 4 + 255) / 256, 256>>>(ei);
    cudaEventRecord(ev_csr, 0);

    // side stream: t=1 half (needs gemm [in-order] + CSR [event])
    cudaStreamWaitEvent(s_side, ev_csr, 0);
    k_agg<<<(NN + 7) / 8, 256, 0, s_side>>>(att, bias, NN, MROWS);
    k_proj<<<(NN + 63) / 64, 256, PROJ_SMEM, s_side>>>(
        x, Wp, bp, gam, bet, out, NN, MROWS);
    cudaEventRecord(ev_done, s_side);

    // main stream: t=0 half (needs gemm via ev_join; CSR in-order)
    cudaStreamWaitEvent(0, ev_join, 0);
    k_agg<<<(NN + 7) / 8, 256>>>(att, bias, 0, NN);
    k_proj<<<(NN + 63) / 64, 256, PROJ_SMEM>>>(x, Wp, bp, gam, bet, out, 0, NN);

    cudaStreamWaitEvent(0, ev_done, 0);
}